// round 4
// baseline (speedup 1.0000x reference)
#include <cuda_runtime.h>
#include <math.h>

typedef unsigned long long ull;

#define BS 32
#define NRR 100
#define IND 2048
#define QDIM 1024
#define CCH 256
#define C1 128
#define C2 64

// ------------- scratch (device globals; no allocations) -------------
__device__ float g_Qp[BS * CCH];
__device__ float g_Xp[BS * NRR * CCH];
__device__ float g_logits[2 * BS * NRR * NRR];
__device__ float g_S[BS * NRR * NRR];

// ------------- f32x2 helpers -------------
__device__ __forceinline__ ull pack2(float x) {
    ull r; asm("mov.b64 %0, {%1,%1};" : "=l"(r) : "f"(x)); return r;
}
__device__ __forceinline__ ull fma2(ull a, ull b, ull c) {
    ull d; asm("fma.rn.f32x2 %0, %1, %2, %3;" : "=l"(d) : "l"(a), "l"(b), "l"(c)); return d;
}
__device__ __forceinline__ void unpack2(ull v, float& lo, float& hi) {
    asm("mov.b64 {%0,%1}, %2;" : "=f"(lo), "=f"(hi) : "l"(v));
}

// ================= K1: Qp = Q @ Wq + bq =================
__global__ void k1_qp(const float* __restrict__ Q, const float* __restrict__ Wq,
                      const float* __restrict__ bq) {
    __shared__ float qs[QDIM];
    int b = blockIdx.x, tid = threadIdx.x;
    for (int k = tid; k < QDIM; k += 256) qs[k] = Q[b * QDIM + k];
    __syncthreads();
    float a0 = 0.f, a1 = 0.f, a2 = 0.f, a3 = 0.f;
    for (int k = 0; k < QDIM; k += 4) {
        a0 += qs[k + 0] * Wq[(k + 0) * CCH + tid];
        a1 += qs[k + 1] * Wq[(k + 1) * CCH + tid];
        a2 += qs[k + 2] * Wq[(k + 2) * CCH + tid];
        a3 += qs[k + 3] * Wq[(k + 3) * CCH + tid];
    }
    g_Qp[b * CCH + tid] = bq[tid] + ((a0 + a1) + (a2 + a3));
}

// ================= K2: Xp = X @ Wv + bv + Qp[b] =================
// M=3200, N=256, K=2048. Tile 64x64, 256 threads, 4x4 micro.
__global__ __launch_bounds__(256) void k2_xp(const float* __restrict__ X,
                                             const float* __restrict__ Wv,
                                             const float* __restrict__ bv) {
    __shared__ float As[64][17];
    __shared__ float Bs[16][68];
    int tid = threadIdx.x;
    int m0 = blockIdx.y * 64, n0 = blockIdx.x * 64;
    int tx = tid & 15, ty = tid >> 4;
    int arow = tid >> 2, ak = (tid & 3) << 2;
    int bk = tid >> 4, bc = (tid & 15) << 2;
    float acc[4][4] = {};
    for (int kc = 0; kc < IND; kc += 16) {
        float4 av = *(const float4*)&X[(m0 + arow) * IND + kc + ak];
        float4 bw = *(const float4*)&Wv[(kc + bk) * CCH + n0 + bc];
        __syncthreads();
        As[arow][ak + 0] = av.x; As[arow][ak + 1] = av.y;
        As[arow][ak + 2] = av.z; As[arow][ak + 3] = av.w;
        *(float4*)&Bs[bk][bc] = bw;
        __syncthreads();
#pragma unroll
        for (int k = 0; k < 16; k++) {
            float a[4];
#pragma unroll
            for (int r = 0; r < 4; r++) a[r] = As[ty * 4 + r][k];
            float4 b4 = *(float4*)&Bs[k][tx * 4];
#pragma unroll
            for (int r = 0; r < 4; r++) {
                acc[r][0] += a[r] * b4.x; acc[r][1] += a[r] * b4.y;
                acc[r][2] += a[r] * b4.z; acc[r][3] += a[r] * b4.w;
            }
        }
    }
#pragma unroll
    for (int r = 0; r < 4; r++) {
        int m = m0 + ty * 4 + r;
        int bidx = m / NRR;
#pragma unroll
        for (int c = 0; c < 4; c++) {
            int n = n0 + tx * 4 + c;
            g_Xp[m * CCH + n] = acc[r][c] + bv[n] + g_Qp[bidx * CCH + n];
        }
    }
}

// ================= K3: fused pair-MLP (both branches) =================
// Tile: 16 i x 8 j = 128 pairs. Upper-tri tiles only (jt >= 2*it). 49 tiles/batch.
#define XIS 257
struct SM3 {
    float Xi[16 * XIS];
    float Xj[8 * XIS];
    float H1[128 * 129];
    float H2[128 * 65];
    float Ws[32 * 128];
    float W2s[128 * 64];
    float W3s[64];
};

__global__ __launch_bounds__(256, 1) void k3_pair(
    const float* __restrict__ W01, const float* __restrict__ b01,
    const float* __restrict__ W02, const float* __restrict__ b02,
    const float* __restrict__ W03, const float* __restrict__ b03,
    const float* __restrict__ W1, const float* __restrict__ b1,
    const float* __restrict__ W2, const float* __restrict__ b2,
    const float* __restrict__ W3, const float* __restrict__ b3) {
    extern __shared__ char raw[];
    SM3* sm = (SM3*)raw;
    int tid = threadIdx.x;
    int b = blockIdx.x / 49;
    int tile = blockIdx.x % 49;
    int it = 0, u = tile, cnt = 13;
    while (u >= cnt) { u -= cnt; it++; cnt -= 2; }
    int jt = 2 * it + u;
    int i0 = it * 16, j0 = jt * 8;

    // load Xi (16 rows), Xj (8 rows) of Xp[b]
    for (int t = tid; t < 16 * 256; t += 256) {
        int row = t >> 8, k = t & 255;
        int gi = i0 + row;
        sm->Xi[row * XIS + k] = (gi < NRR) ? g_Xp[(b * NRR + gi) * CCH + k] : 0.f;
    }
    for (int t = tid; t < 8 * 256; t += 256) {
        int row = t >> 8, k = t & 255;
        int gj = j0 + row;
        sm->Xj[row * XIS + k] = (gj < NRR) ? g_Xp[(b * NRR + gj) * CCH + k] : 0.f;
    }

    int rg = tid >> 4, cg = tid & 15;
    int c0 = cg * 8;

    for (int br = 0; br < 2; br++) {
        const float* Wa = br ? W1 : W01;  const float* ba = br ? b1 : b01;
        const float* Wb = br ? W2 : W02;  const float* bb = br ? b2 : b02;
        const float* Wc = br ? W3 : W03;  const float* bc = br ? b3 : b03;

        // ---- GEMM1: [128 pairs x 128] = P[128 x 256] @ Wa[256 x 128] ----
        ull acc[8][4];
#pragma unroll
        for (int r = 0; r < 8; r++)
#pragma unroll
            for (int n = 0; n < 4; n++) acc[r][n] = 0ULL;

        for (int kc = 0; kc < 8; kc++) {
            __syncthreads();
            for (int t = tid; t < 1024; t += 256)
                ((float4*)sm->Ws)[t] = ((const float4*)(Wa + kc * 4096))[t];
            __syncthreads();
#pragma unroll 4
            for (int k = 0; k < 32; k++) {
                int kk = kc * 32 + k;
                float xi = sm->Xi[rg * XIS + kk];
                ull a[8];
#pragma unroll
                for (int r = 0; r < 8; r++)
                    a[r] = pack2(xi * sm->Xj[r * XIS + kk]);
                ull bf[4];
#pragma unroll
                for (int n = 0; n < 4; n++)
                    bf[n] = *(const ull*)&sm->Ws[k * 128 + c0 + n * 2];
#pragma unroll
                for (int r = 0; r < 8; r++)
#pragma unroll
                    for (int n = 0; n < 4; n++)
                        acc[r][n] = fma2(a[r], bf[n], acc[r][n]);
            }
        }
        // epilogue: bias + relu -> H1; also stage W2s, W3s
        float bia[8];
#pragma unroll
        for (int t = 0; t < 8; t++) bia[t] = ba[c0 + t];
#pragma unroll
        for (int r = 0; r < 8; r++) {
            int m = rg * 8 + r;
#pragma unroll
            for (int n = 0; n < 4; n++) {
                float lo, hi; unpack2(acc[r][n], lo, hi);
                sm->H1[m * 129 + c0 + 2 * n]     = fmaxf(lo + bia[2 * n], 0.f);
                sm->H1[m * 129 + c0 + 2 * n + 1] = fmaxf(hi + bia[2 * n + 1], 0.f);
            }
        }
        for (int t = tid; t < 2048; t += 256)
            ((float4*)sm->W2s)[t] = ((const float4*)Wb)[t];
        if (tid < 64) sm->W3s[tid] = Wc[tid];
        __syncthreads();

        // ---- GEMM2: [128 x 64] = H1[128 x 128] @ Wb[128 x 64] ----
        ull acc2[8][2];
#pragma unroll
        for (int r = 0; r < 8; r++) { acc2[r][0] = 0ULL; acc2[r][1] = 0ULL; }
        int c20 = cg * 4;
#pragma unroll 4
        for (int k = 0; k < 128; k++) {
            ull b2v[2];
            b2v[0] = *(const ull*)&sm->W2s[k * 64 + c20];
            b2v[1] = *(const ull*)&sm->W2s[k * 64 + c20 + 2];
#pragma unroll
            for (int r = 0; r < 8; r++) {
                ull av = pack2(sm->H1[(rg * 8 + r) * 129 + k]);
                acc2[r][0] = fma2(av, b2v[0], acc2[r][0]);
                acc2[r][1] = fma2(av, b2v[1], acc2[r][1]);
            }
        }
        float bib[4];
#pragma unroll
        for (int t = 0; t < 4; t++) bib[t] = bb[c20 + t];
#pragma unroll
        for (int r = 0; r < 8; r++) {
            int m = rg * 8 + r;
#pragma unroll
            for (int n = 0; n < 2; n++) {
                float lo, hi; unpack2(acc2[r][n], lo, hi);
                sm->H2[m * 65 + c20 + 2 * n]     = fmaxf(lo + bib[2 * n], 0.f);
                sm->H2[m * 65 + c20 + 2 * n + 1] = fmaxf(hi + bib[2 * n + 1], 0.f);
            }
        }
        __syncthreads();

        // ---- GEMM3 + symmetric residual + logit write ----
        if (tid < 128) {
            int m = tid;
            float s = bc[0];
#pragma unroll 8
            for (int k = 0; k < 64; k++) s += sm->H2[m * 65 + k] * sm->W3s[k];
            float v = 2.f * fmaxf(s, 0.f);
            int i = i0 + (m >> 3), j = j0 + (m & 7);
            if (i < NRR && j < NRR) {
                float* L = g_logits + (br * BS + b) * (NRR * NRR);
                L[i * NRR + j] = v;
                L[j * NRR + i] = v;
            }
        }
    }
}

// ================= K4: softmax per (b,branch) + combine =================
__global__ void k4_softmax() {
    int b = blockIdx.x, tid = threadIdx.x;
    __shared__ float red[8];
    __shared__ float bm[2], bsum[2];
    const int NE = NRR * NRR;
    for (int br = 0; br < 2; br++) {
        const float* L = g_logits + (br * BS + b) * NE;
        float m = -1e30f;
        for (int e = tid; e < NE; e += 256) m = fmaxf(m, L[e]);
        for (int o = 16; o; o >>= 1) m = fmaxf(m, __shfl_xor_sync(~0u, m, o));
        if ((tid & 31) == 0) red[tid >> 5] = m;
        __syncthreads();
        if (tid == 0) {
            float a = red[0];
            for (int w = 1; w < 8; w++) a = fmaxf(a, red[w]);
            bm[br] = a;
        }
        __syncthreads();
        float mm = bm[br];
        float s = 0.f;
        for (int e = tid; e < NE; e += 256) s += expf(L[e] - mm);
        for (int o = 16; o; o >>= 1) s += __shfl_xor_sync(~0u, s, o);
        if ((tid & 31) == 0) red[tid >> 5] = s;
        __syncthreads();
        if (tid == 0) {
            float a = red[0];
            for (int w = 1; w < 8; w++) a += red[w];
            bsum[br] = a;
        }
        __syncthreads();
    }
    float m0 = bm[0], is0 = 1.f / bsum[0];
    float m1 = bm[1], is1 = 1.f / bsum[1];
    const float* L0 = g_logits + b * NE;
    const float* L1 = g_logits + (BS + b) * NE;
    float* S = g_S + b * NE;
    for (int e = tid; e < NE; e += 256)
        S[e] = 0.5f * (expf(L0[e] - m0) * is0 + expf(L1[e] - m1) * is1);
}

// ================= K5: out = S @ X * 0.5 (already halved in S combine? no) =================
// S already includes the (rm0+rm1)/2 factor (0.5 applied in k4), so out = S @ X.
__global__ __launch_bounds__(128) void k5_out(const float* __restrict__ X,
                                              float* __restrict__ out) {
    __shared__ float Ss[NRR * NRR];
    int b = blockIdx.y;
    int c0 = blockIdx.x * 512 + threadIdx.x * 4;
    for (int e = threadIdx.x; e < NRR * NRR; e += 128) Ss[e] = g_S[b * NRR * NRR + e];
    __syncthreads();
    const float* Xb = X + b * NRR * IND;
    for (int i0 = 0; i0 < NRR; i0 += 25) {
        float4 acc[25];
#pragma unroll
        for (int ii = 0; ii < 25; ii++) acc[ii] = make_float4(0.f, 0.f, 0.f, 0.f);
        for (int j = 0; j < NRR; j++) {
            float4 xv = *(const float4*)&Xb[j * IND + c0];
#pragma unroll
            for (int ii = 0; ii < 25; ii++) {
                float s = Ss[(i0 + ii) * NRR + j];
                acc[ii].x += s * xv.x; acc[ii].y += s * xv.y;
                acc[ii].z += s * xv.z; acc[ii].w += s * xv.w;
            }
        }
#pragma unroll
        for (int ii = 0; ii < 25; ii++)
            *(float4*)&out[(b * NRR + i0 + ii) * IND + c0] = acc[ii];
    }
}

// ================= launch =================
extern "C" void kernel_launch(void* const* d_in, const int* in_sizes, int n_in,
                              void* d_out, int out_size) {
    const float* Q   = (const float*)d_in[0];
    const float* X   = (const float*)d_in[1];
    const float* Wv  = (const float*)d_in[2];
    const float* bv  = (const float*)d_in[3];
    const float* Wq  = (const float*)d_in[4];
    const float* bq  = (const float*)d_in[5];
    const float* W01 = (const float*)d_in[6];
    const float* b01 = (const float*)d_in[7];
    const float* W02 = (const float*)d_in[8];
    const float* b02 = (const float*)d_in[9];
    const float* W03 = (const float*)d_in[10];
    const float* b03 = (const float*)d_in[11];
    const float* W1  = (const float*)d_in[12];
    const float* b1  = (const float*)d_in[13];
    const float* W2  = (const float*)d_in[14];
    const float* b2  = (const float*)d_in[15];
    const float* W3  = (const float*)d_in[16];
    const float* b3  = (const float*)d_in[17];
    float* out = (float*)d_out;

    cudaFuncSetAttribute(k3_pair, cudaFuncAttributeMaxDynamicSharedMemorySize,
                         (int)sizeof(SM3));

    k1_qp<<<BS, 256>>>(Q, Wq, bq);
    k2_xp<<<dim3(4, 50), 256>>>(X, Wv, bv);
    k3_pair<<<BS * 49, 256, sizeof(SM3)>>>(W01, b01, W02, b02, W03, b03,
                                           W1, b1, W2, b2, W3, b3);
    k4_softmax<<<BS, 256>>>();
    k5_out<<<dim3(4, BS), 128>>>(X, out);
}

// round 6
// speedup vs baseline: 1.9284x; 1.9284x over previous
#include <cuda_runtime.h>
#include <cuda_bf16.h>
#include <math.h>
#include <stdint.h>

typedef unsigned long long ull;

#define BS 32
#define NRR 100
#define IND 2048
#define QDIM 1024
#define CCH 256

__device__ float g_Qp[BS * CCH];
__device__ float g_Xp[BS * NRR * CCH];
__device__ float g_logits[2 * BS * NRR * NRR];
__device__ float g_S[BS * NRR * NRR];
// pre-transposed [br][n][k] bf16 hi/lo splits
__device__ __align__(16) unsigned short g_W1h[2 * 128 * 256];
__device__ __align__(16) unsigned short g_W1l[2 * 128 * 256];
__device__ __align__(16) unsigned short g_W2h[2 * 64 * 128];
__device__ __align__(16) unsigned short g_W2l[2 * 64 * 128];

__device__ __forceinline__ ull pack2(float x) {
    ull r; asm("mov.b64 %0, {%1,%1};" : "=l"(r) : "f"(x)); return r;
}
__device__ __forceinline__ ull fma2(ull a, ull b, ull c) {
    ull d; asm("fma.rn.f32x2 %0, %1, %2, %3;" : "=l"(d) : "l"(a), "l"(b), "l"(c)); return d;
}
__device__ __forceinline__ void unpack2(ull v, float& lo, float& hi) {
    asm("mov.b64 {%0,%1}, %2;" : "=f"(lo), "=f"(hi) : "l"(v));
}
__device__ __forceinline__ uint32_t smem_u32(const void* p) {
    uint32_t a;
    asm("{ .reg .u64 t; cvta.to.shared.u64 t, %1; cvt.u32.u64 %0, t; }" : "=r"(a) : "l"(p));
    return a;
}
__device__ __forceinline__ void bsplit(float f0, float f1, uint32_t& hp, uint32_t& lp) {
    asm("cvt.rn.satfinite.bf16x2.f32 %0, %1, %2;" : "=r"(hp) : "f"(f1), "f"(f0));
    float l0 = f0 - __uint_as_float(hp << 16);
    float l1 = f1 - __uint_as_float(hp & 0xFFFF0000u);
    asm("cvt.rn.satfinite.bf16x2.f32 %0, %1, %2;" : "=r"(lp) : "f"(l1), "f"(l0));
}

#define LDSM4(r0, r1, r2, r3, addr) \
    asm volatile("ldmatrix.sync.aligned.m8n8.x4.shared.b16 {%0,%1,%2,%3}, [%4];" \
        : "=r"(r0), "=r"(r1), "=r"(r2), "=r"(r3) : "r"(addr))

#define MMA16816(d, a0, a1, a2, a3, b0, b1) \
    asm volatile("mma.sync.aligned.m16n8k16.row.col.f32.bf16.bf16.f32 " \
        "{%0,%1,%2,%3},{%4,%5,%6,%7},{%8,%9},{%0,%1,%2,%3};" \
        : "+f"((d)[0]), "+f"((d)[1]), "+f"((d)[2]), "+f"((d)[3]) \
        : "r"(a0), "r"(a1), "r"(a2), "r"(a3), "r"(b0), "r"(b1))

// ============ K0: weight transpose + bf16 hi/lo split ============
__global__ void k0_prep(const float* __restrict__ W01, const float* __restrict__ W1f,
                        const float* __restrict__ W02, const float* __restrict__ W2f) {
    int idx = blockIdx.x * 256 + threadIdx.x;
    if (idx < 65536) {
        int br = idx >> 15, rem = idx & 32767, n = rem >> 8, k = rem & 255;
        float x = (br ? W1f : W01)[k * 128 + n];
        __nv_bfloat16 hb = __float2bfloat16_rn(x);
        __nv_bfloat16 lb = __float2bfloat16_rn(x - __bfloat162float(hb));
        g_W1h[idx] = __bfloat16_as_ushort(hb);
        g_W1l[idx] = __bfloat16_as_ushort(lb);
    } else if (idx < 81920) {
        int i2 = idx - 65536;
        int br = i2 >> 13, rem = i2 & 8191, n = rem >> 7, k = rem & 127;
        float x = (br ? W2f : W02)[k * 64 + n];
        __nv_bfloat16 hb = __float2bfloat16_rn(x);
        __nv_bfloat16 lb = __float2bfloat16_rn(x - __bfloat162float(hb));
        g_W2h[i2] = __bfloat16_as_ushort(hb);
        g_W2l[i2] = __bfloat16_as_ushort(lb);
    }
}

// ============ K1: Qp = Q @ Wq + bq ============
__global__ void k1_qp(const float* __restrict__ Q, const float* __restrict__ Wq,
                      const float* __restrict__ bq) {
    __shared__ float qs[QDIM];
    int b = blockIdx.x, tid = threadIdx.x;
    for (int k = tid; k < QDIM; k += 256) qs[k] = Q[b * QDIM + k];
    __syncthreads();
    float a0 = 0.f, a1 = 0.f, a2 = 0.f, a3 = 0.f;
    for (int k = 0; k < QDIM; k += 4) {
        a0 += qs[k + 0] * Wq[(k + 0) * CCH + tid];
        a1 += qs[k + 1] * Wq[(k + 1) * CCH + tid];
        a2 += qs[k + 2] * Wq[(k + 2) * CCH + tid];
        a3 += qs[k + 3] * Wq[(k + 3) * CCH + tid];
    }
    g_Qp[b * CCH + tid] = bq[tid] + ((a0 + a1) + (a2 + a3));
}

// ============ K2: Xp = X @ Wv + bv + Qp[b] (f32x2) ============
__global__ __launch_bounds__(256) void k2_xp(const float* __restrict__ X,
                                             const float* __restrict__ Wv,
                                             const float* __restrict__ bv) {
    __shared__ float As[64][17];
    __shared__ float Bs[16][68];
    int tid = threadIdx.x;
    int m0 = blockIdx.y * 64, n0 = blockIdx.x * 64;
    int tx = tid & 15, ty = tid >> 4;
    int arow = tid >> 2, ak = (tid & 3) << 2;
    int bk = tid >> 4, bc = (tid & 15) << 2;
    ull acc[4][2];
#pragma unroll
    for (int r = 0; r < 4; r++) { acc[r][0] = 0ULL; acc[r][1] = 0ULL; }
    for (int kc = 0; kc < IND; kc += 16) {
        float4 av = *(const float4*)&X[(m0 + arow) * IND + kc + ak];
        float4 bw = *(const float4*)&Wv[(kc + bk) * CCH + n0 + bc];
        __syncthreads();
        As[arow][ak + 0] = av.x; As[arow][ak + 1] = av.y;
        As[arow][ak + 2] = av.z; As[arow][ak + 3] = av.w;
        *(float4*)&Bs[bk][bc] = bw;
        __syncthreads();
#pragma unroll
        for (int k = 0; k < 16; k++) {
            ull b0 = *(const ull*)&Bs[k][tx * 4];
            ull b1v = *(const ull*)&Bs[k][tx * 4 + 2];
#pragma unroll
            for (int r = 0; r < 4; r++) {
                ull ar = pack2(As[ty * 4 + r][k]);
                acc[r][0] = fma2(ar, b0, acc[r][0]);
                acc[r][1] = fma2(ar, b1v, acc[r][1]);
            }
        }
    }
#pragma unroll
    for (int r = 0; r < 4; r++) {
        int m = m0 + ty * 4 + r, bidx = m / NRR;
#pragma unroll
        for (int h = 0; h < 2; h++) {
            float lo, hi; unpack2(acc[r][h], lo, hi);
            int n = n0 + tx * 4 + 2 * h;
            g_Xp[m * CCH + n]     = lo + bv[n] + g_Qp[bidx * CCH + n];
            g_Xp[m * CCH + n + 1] = hi + bv[n + 1] + g_Qp[bidx * CCH + n + 1];
        }
    }
}

// ============ K3: fused pair-MLP on mma.sync bf16 (3-split) ============
// smem byte offsets
#define OFF_XI  0           // 16 x 260 f32 = 16640
#define OFF_XJ  16640       // 8 x 260 f32 = 8320
#define OFF_B1S 24960       // 256 f32
#define OFF_B2S 25984       // 128 f32
#define OFF_W3S 26496       // 128 f32
#define OFF_B3S 27008       // 2 f32 (+pad)
#define OFF_PH  27136       // 128 x 144 = 18432
#define OFF_PL  45568
#define OFF_W1H 64000       // 128 x 144 = 18432
#define OFF_W1L 82432
#define OFF_H1H 100864      // 128 x 272 = 34816
#define OFF_H1L 135680
#define OFF_W2H 170496      // 64 x 272 = 17408
#define OFF_W2L 187904
#define K3_SMEM 205440

__global__ __launch_bounds__(256, 1) void k3_pair(
    const float* __restrict__ b01, const float* __restrict__ b02,
    const float* __restrict__ W03, const float* __restrict__ b03,
    const float* __restrict__ b1f, const float* __restrict__ b2f,
    const float* __restrict__ W3f, const float* __restrict__ b3f) {
    extern __shared__ char raw[];
    uint32_t base_u = smem_u32(raw);

    int tid = threadIdx.x, wid = tid >> 5, lane = tid & 31;
    int b = blockIdx.x / 49;
    int tile = blockIdx.x % 49;
    int it = 0, u = tile, cnt = 13;
    while (u >= cnt) { u -= cnt; it++; cnt -= 2; }
    int jt = 2 * it + u;
    int i0 = it * 16, j0 = jt * 8;

    float* Xi = (float*)(raw + OFF_XI);
    float* Xj = (float*)(raw + OFF_XJ);
    float* b1s = (float*)(raw + OFF_B1S);
    float* b2s = (float*)(raw + OFF_B2S);
    float* w3s = (float*)(raw + OFF_W3S);
    float* b3s = (float*)(raw + OFF_B3S);

    float4 z = make_float4(0.f, 0.f, 0.f, 0.f);
    for (int t = tid; t < 16 * 64; t += 256) {
        int row = t >> 6, c4 = (t & 63) * 4, gi = i0 + row;
        *(float4*)&Xi[row * 260 + c4] =
            (gi < NRR) ? *(const float4*)&g_Xp[(b * NRR + gi) * CCH + c4] : z;
    }
    for (int t = tid; t < 8 * 64; t += 256) {
        int row = t >> 6, c4 = (t & 63) * 4, gj = j0 + row;
        *(float4*)&Xj[row * 260 + c4] =
            (gj < NRR) ? *(const float4*)&g_Xp[(b * NRR + gj) * CCH + c4] : z;
    }
    if (tid < 128) { b1s[tid] = b01[tid]; b1s[128 + tid] = b1f[tid]; }
    if (tid < 64) {
        b2s[tid] = b02[tid]; b2s[64 + tid] = b2f[tid];
        w3s[tid] = W03[tid]; w3s[64 + tid] = W3f[tid];
    }
    if (tid == 0) { b3s[0] = b03[0]; b3s[1] = b3f[0]; }

    // per-thread fragment geometry
    int m0w = wid * 16;
    uint32_t g = lane >> 3, r = lane & 7;
    // A lanes: row = m0w + (g&1)*8 + r ; k byte off = (g>>1)*16
    uint32_t a_row = (uint32_t)(m0w + (int)(g & 1) * 8 + (int)r);
    uint32_t a_k16 = (g >> 1) * 16;
    // B lanes: row = nf*16 + (g>>1)*8 + r ; k byte off = (g&1)*16
    uint32_t b_row = (g >> 1) * 8 + r;
    uint32_t b_k16 = (g & 1) * 16;

    // P build geometry
    int mB = tid >> 1, ksB = (tid & 1) * 32;
    const float* xir = Xi + (mB >> 3) * 260;
    const float* xjr = Xj + (mB & 7) * 260;
    char* phB = raw + OFF_PH + mB * 144 + ksB * 2;
    char* plB = raw + OFF_PL + mB * 144 + ksB * 2;

    for (int br = 0; br < 2; br++) {
        float acc1[64];
#pragma unroll
        for (int q = 0; q < 64; q++) acc1[q] = 0.f;

        // ---- GEMM1: C[128,128] = P[128,256] @ W1[br]^T, 4 k-chunks of 64 ----
        for (int c = 0; c < 4; c++) {
            __syncthreads();
            // build P chunk (hi/lo planes)
#pragma unroll
            for (int kk = 0; kk < 32; kk += 2) {
                int k = c * 64 + ksB + kk;
                uint32_t hp, lp;
                bsplit(xir[k] * xjr[k], xir[k + 1] * xjr[k + 1], hp, lp);
                *(uint32_t*)(phB + kk * 2) = hp;
                *(uint32_t*)(plB + kk * 2) = lp;
            }
            // stage W1 chunk [n=128][k=64] hi/lo
            for (int t = tid; t < 2048; t += 256) {
                int pl = t >> 10, e = t & 1023, n = e >> 3, s = e & 7;
                const unsigned short* src =
                    (pl ? g_W1l : g_W1h) + br * 32768 + n * 256 + c * 64 + s * 8;
                *(uint4*)(raw + (pl ? OFF_W1L : OFF_W1H) + n * 144 + s * 16) =
                    *(const uint4*)src;
            }
            __syncthreads();
#pragma unroll
            for (int kf = 0; kf < 4; kf++) {
                uint32_t ah0, ah1, ah2, ah3, al0, al1, al2, al3;
                uint32_t aA = base_u + a_row * 144 + kf * 32 + a_k16;
                LDSM4(ah0, ah1, ah2, ah3, aA + OFF_PH);
                LDSM4(al0, al1, al2, al3, aA + OFF_PL);
#pragma unroll
                for (int nf = 0; nf < 8; nf++) {
                    uint32_t bh0, bh1, bh2, bh3, bl0, bl1, bl2, bl3;
                    uint32_t aB = base_u + (nf * 16 + b_row) * 144 + kf * 32 + b_k16;
                    LDSM4(bh0, bh1, bh2, bh3, aB + OFF_W1H);
                    LDSM4(bl0, bl1, bl2, bl3, aB + OFF_W1L);
                    float* d0 = &acc1[nf * 8];
                    MMA16816(d0, ah0, ah1, ah2, ah3, bh0, bh1);
                    MMA16816(d0, ah0, ah1, ah2, ah3, bl0, bl1);
                    MMA16816(d0, al0, al1, al2, al3, bh0, bh1);
                    float* d1 = &acc1[nf * 8 + 4];
                    MMA16816(d1, ah0, ah1, ah2, ah3, bh2, bh3);
                    MMA16816(d1, ah0, ah1, ah2, ah3, bl2, bl3);
                    MMA16816(d1, al0, al1, al2, al3, bh2, bh3);
                }
            }
        }

        // ---- H1 epilogue: bias + relu + re-split -> smem planes ----
        {
            int rowA = m0w + (lane >> 2);
            char* h1h = raw + OFF_H1H;
            char* h1l = raw + OFF_H1L;
#pragma unroll
            for (int f = 0; f < 16; f++) {
                int n = f * 8 + (lane & 3) * 2;
                float f0 = fmaxf(acc1[f * 4 + 0] + b1s[br * 128 + n], 0.f);
                float f1 = fmaxf(acc1[f * 4 + 1] + b1s[br * 128 + n + 1], 0.f);
                uint32_t hp, lp;
                bsplit(f0, f1, hp, lp);
                *(uint32_t*)(h1h + rowA * 272 + n * 2) = hp;
                *(uint32_t*)(h1l + rowA * 272 + n * 2) = lp;
                f0 = fmaxf(acc1[f * 4 + 2] + b1s[br * 128 + n], 0.f);
                f1 = fmaxf(acc1[f * 4 + 3] + b1s[br * 128 + n + 1], 0.f);
                bsplit(f0, f1, hp, lp);
                *(uint32_t*)(h1h + (rowA + 8) * 272 + n * 2) = hp;
                *(uint32_t*)(h1l + (rowA + 8) * 272 + n * 2) = lp;
            }
        }
        // stage W2 [n=64][k=128] hi/lo
        for (int t = tid; t < 2048; t += 256) {
            int pl = t >> 10, e = t & 1023, n = e >> 4, s = e & 15;
            const unsigned short* src = (pl ? g_W2l : g_W2h) + br * 8192 + n * 128 + s * 8;
            *(uint4*)(raw + (pl ? OFF_W2L : OFF_W2H) + n * 272 + s * 16) = *(const uint4*)src;
        }
        __syncthreads();

        // ---- GEMM2: C2[128,64] = H1[128,128] @ W2[br]^T ----
        float acc2[32];
#pragma unroll
        for (int q = 0; q < 32; q++) acc2[q] = 0.f;
#pragma unroll
        for (int kf = 0; kf < 8; kf++) {
            uint32_t ah0, ah1, ah2, ah3, al0, al1, al2, al3;
            uint32_t aA = base_u + a_row * 272 + kf * 32 + a_k16;
            LDSM4(ah0, ah1, ah2, ah3, aA + OFF_H1H);
            LDSM4(al0, al1, al2, al3, aA + OFF_H1L);
#pragma unroll
            for (int nf = 0; nf < 4; nf++) {
                uint32_t bh0, bh1, bh2, bh3, bl0, bl1, bl2, bl3;
                uint32_t aB = base_u + (nf * 16 + b_row) * 272 + kf * 32 + b_k16;
                LDSM4(bh0, bh1, bh2, bh3, aB + OFF_W2H);
                LDSM4(bl0, bl1, bl2, bl3, aB + OFF_W2L);
                float* d0 = &acc2[nf * 8];
                MMA16816(d0, ah0, ah1, ah2, ah3, bh0, bh1);
                MMA16816(d0, ah0, ah1, ah2, ah3, bl0, bl1);
                MMA16816(d0, al0, al1, al2, al3, bh0, bh1);
                float* d1 = &acc2[nf * 8 + 4];
                MMA16816(d1, ah0, ah1, ah2, ah3, bh2, bh3);
                MMA16816(d1, ah0, ah1, ah2, ah3, bl2, bl3);
                MMA16816(d1, al0, al1, al2, al3, bh2, bh3);
            }
        }

        // ---- GEMM3: dot(relu(H2+b2), W3) via quad-shuffle reduce ----
        {
            float p0 = 0.f, p1 = 0.f;
#pragma unroll
            for (int f = 0; f < 8; f++) {
                int n = f * 8 + (lane & 3) * 2;
                float w0 = w3s[br * 64 + n], w1 = w3s[br * 64 + n + 1];
                float c0 = b2s[br * 64 + n], c1 = b2s[br * 64 + n + 1];
                p0 += fmaxf(acc2[f * 4 + 0] + c0, 0.f) * w0
                    + fmaxf(acc2[f * 4 + 1] + c1, 0.f) * w1;
                p1 += fmaxf(acc2[f * 4 + 2] + c0, 0.f) * w0
                    + fmaxf(acc2[f * 4 + 3] + c1, 0.f) * w1;
            }
            p0 += __shfl_xor_sync(~0u, p0, 1); p0 += __shfl_xor_sync(~0u, p0, 2);
            p1 += __shfl_xor_sync(~0u, p1, 1); p1 += __shfl_xor_sync(~0u, p1, 2);
            if ((lane & 3) == 0) {
                int q = lane >> 2;
                float* L = g_logits + (br * BS + b) * (NRR * NRR);
                int m1 = m0w + q, m2 = m0w + q + 8;
                float v0 = 2.f * fmaxf(p0 + b3s[br], 0.f);
                float v1 = 2.f * fmaxf(p1 + b3s[br], 0.f);
                int i1 = i0 + (m1 >> 3), j1 = j0 + (m1 & 7);
                int i2 = i0 + (m2 >> 3), j2 = j0 + (m2 & 7);
                if (i1 < NRR && j1 < NRR) { L[i1 * NRR + j1] = v0; L[j1 * NRR + i1] = v0; }
                if (i2 < NRR && j2 < NRR) { L[i2 * NRR + j2] = v1; L[j2 * NRR + i2] = v1; }
            }
        }
    }
}

// ============ K4: softmax per (b,branch) + combine ============
__global__ void k4_softmax() {
    int b = blockIdx.x, tid = threadIdx.x;
    __shared__ float red[8];
    __shared__ float bm[2], bsum[2];
    const int NE = NRR * NRR;
    for (int br = 0; br < 2; br++) {
        const float* L = g_logits + (br * BS + b) * NE;
        float m = -1e30f;
        for (int e = tid; e < NE; e += 256) m = fmaxf(m, L[e]);
        for (int o = 16; o; o >>= 1) m = fmaxf(m, __shfl_xor_sync(~0u, m, o));
        if ((tid & 31) == 0) red[tid >> 5] = m;
        __syncthreads();
        if (tid == 0) {
            float a = red[0];
            for (int w = 1; w < 8; w++) a = fmaxf(a, red[w]);
            bm[br] = a;
        }
        __syncthreads();
        float mm = bm[br], s = 0.f;
        for (int e = tid; e < NE; e += 256) s += expf(L[e] - mm);
        for (int o = 16; o; o >>= 1) s += __shfl_xor_sync(~0u, s, o);
        if ((tid & 31) == 0) red[tid >> 5] = s;
        __syncthreads();
        if (tid == 0) {
            float a = red[0];
            for (int w = 1; w < 8; w++) a += red[w];
            bsum[br] = a;
        }
        __syncthreads();
    }
    float m0 = bm[0], is0 = 1.f / bsum[0];
    float m1 = bm[1], is1 = 1.f / bsum[1];
    const float* L0 = g_logits + b * NE;
    const float* L1 = g_logits + (BS + b) * NE;
    float* S = g_S + b * NE;
    for (int e = tid; e < NE; e += 256)
        S[e] = 0.5f * (expf(L0[e] - m0) * is0 + expf(L1[e] - m1) * is1);
}

// ============ K5: out = S @ X ============
__global__ __launch_bounds__(128) void k5_out(const float* __restrict__ X,
                                              float* __restrict__ out) {
    __shared__ float Ss[NRR * NRR];
    int b = blockIdx.y;
    int c0 = blockIdx.x * 512 + threadIdx.x * 4;
    for (int e = threadIdx.x; e < NRR * NRR; e += 128) Ss[e] = g_S[b * NRR * NRR + e];
    __syncthreads();
    const float* Xb = X + b * NRR * IND;
    for (int i0 = 0; i0 < NRR; i0 += 25) {
        float4 acc[25];
#pragma unroll
        for (int ii = 0; ii < 25; ii++) acc[ii] = make_float4(0.f, 0.f, 0.f, 0.f);
        for (int j = 0; j < NRR; j++) {
            float4 xv = *(const float4*)&Xb[j * IND + c0];
#pragma unroll
            for (int ii = 0; ii < 25; ii++) {
                float s = Ss[(i0 + ii) * NRR + j];
                acc[ii].x += s * xv.x; acc[ii].y += s * xv.y;
                acc[ii].z += s * xv.z; acc[ii].w += s * xv.w;
            }
        }
#pragma unroll
        for (int ii = 0; ii < 25; ii++)
            *(float4*)&out[(b * NRR + i0 + ii) * IND + c0] = acc[ii];
    }
}

// ============ launch ============
extern "C" void kernel_launch(void* const* d_in, const int* in_sizes, int n_in,
                              void* d_out, int out_size) {
    const float* Q   = (const float*)d_in[0];
    const float* X   = (const float*)d_in[1];
    const float* Wv  = (const float*)d_in[2];
    const float* bv  = (const float*)d_in[3];
    const float* Wq  = (const float*)d_in[4];
    const float* bq  = (const float*)d_in[5];
    const float* W01 = (const float*)d_in[6];
    const float* b01 = (const float*)d_in[7];
    const float* W02 = (const float*)d_in[8];
    const float* b02 = (const float*)d_in[9];
    const float* W03 = (const float*)d_in[10];
    const float* b03 = (const float*)d_in[11];
    const float* W1  = (const float*)d_in[12];
    const float* b1  = (const float*)d_in[13];
    const float* W2  = (const float*)d_in[14];
    const float* b2  = (const float*)d_in[15];
    const float* W3  = (const float*)d_in[16];
    const float* b3  = (const float*)d_in[17];
    float* out = (float*)d_out;

    cudaFuncSetAttribute(k3_pair, cudaFuncAttributeMaxDynamicSharedMemorySize, K3_SMEM);

    k0_prep<<<320, 256>>>(W01, W1, W02, W2);
    k1_qp<<<BS, 256>>>(Q, Wq, bq);
    k2_xp<<<dim3(4, 50), 256>>>(X, Wv, bv);
    k3_pair<<<BS * 49, 256, K3_SMEM>>>(b01, b02, W03, b03, b1, b2, W3, b3);
    k4_softmax<<<BS, 256>>>();
    k5_out<<<dim3(4, BS), 128>>>(X, out);
}